// round 10
// baseline (speedup 1.0000x reference)
#include <cuda_runtime.h>
#include <cstdint>

// HashEmbedding: B*L=819200 tokens, H=2, E=64, out=[emb(64), pv0, pv1] f32
// d_in: words int32[819200], hash_table int32[1000000,2],
//       W f32[100000,64], P f32[1000000,2]

static constexpr int NTOK  = 16384 * 50;   // 819200
static constexpr int EMBED = 64;
static constexpr int OUTW  = EMBED + 2;    // 66
static constexpr int TPW   = 8;            // tokens per group
static constexpr int TPB   = 256;
static constexpr int NGROUPS = NTOK / TPW; // 102400

// Persistent single-wave grid: 148 SMs x 7 blocks. launch_bounds(,7) caps
// regs at 36 — enough for R7's 32-reg body PLUS loop state (the (,8)/32-reg
// version spilled a[]/b[] to local and doubled l1tex work).
static constexpr int BLOCKS_PER_SM = 7;
static constexpr int GRID = 148 * BLOCKS_PER_SM;   // 1036 blocks -> 8288 warps

__global__ void __launch_bounds__(TPB, BLOCKS_PER_SM)
hash_embedding_kernel(const int*    __restrict__ words,
                      const int2*   __restrict__ hash_table,
                      const float*  __restrict__ W,
                      const float2* __restrict__ P2,
                      float*        __restrict__ out)
{
    const int gwarp       = (blockIdx.x * TPB + threadIdx.x) >> 5;
    const int lane        = threadIdx.x & 31;
    const int total_warps = (GRID * TPB) >> 5;
    const float* Pf = reinterpret_cast<const float*>(P2);

    for (int grp = gwarp; grp < NGROUPS; grp += total_warps) {
        const int base = grp * TPW;

        // ---- Distributed scalar phase: lane t (mod 8) owns token base+t.
        // Replicated addrs dedup in-warp: one LDG per stage covers 8 tokens. ----
        const int    tok = base + (lane & 7);
        const int    w   = __ldg(&words[tok]);
        const int2   h   = __ldg(&hash_table[w]);
        const float2 pwv = __ldg(&P2[w]);

        if (lane < TPW) {
            float2 pv;
            pv.x = __ldg(&Pf[(size_t)h.x * 2 + 0]);
            pv.y = __ldg(&Pf[(size_t)h.y * 2 + 1]);
            *reinterpret_cast<float2*>(out + (size_t)tok * OUTW + EMBED) = pv;
        }

        // ---- Burst-issue 16 W-row gathers (8B/lane, coalesced 256B rows);
        // scalars travel via SHFL (ALU pipe), not LSU broadcasts. ----
        float2 a[TPW], b[TPW];
#pragma unroll
        for (int t = 0; t < TPW; t++) {
            const int hx = __shfl_sync(0xffffffffu, h.x, t);
            const int hy = __shfl_sync(0xffffffffu, h.y, t);
            a[t] = __ldg(reinterpret_cast<const float2*>(W + (size_t)hx * EMBED) + lane);
            b[t] = __ldg(reinterpret_cast<const float2*>(W + (size_t)hy * EMBED) + lane);
        }

        // ---- Consume in order (frees a[t]/b[t] early), store. ----
#pragma unroll
        for (int t = 0; t < TPW; t++) {
            const float px = __shfl_sync(0xffffffffu, pwv.x, t);
            const float py = __shfl_sync(0xffffffffu, pwv.y, t);
            float2 e;
            e.x = fmaf(a[t].x, px, b[t].x * py);
            e.y = fmaf(a[t].y, px, b[t].y * py);
            float* o = out + (size_t)(base + t) * OUTW;   // 264B stride, 8B aligned
            reinterpret_cast<float2*>(o)[lane] = e;       // cols 0..63
        }
    }
}

extern "C" void kernel_launch(void* const* d_in, const int* in_sizes, int n_in,
                              void* d_out, int out_size)
{
    const int*    words      = (const int*)d_in[0];
    const int2*   hash_table = (const int2*)d_in[1];
    const float*  W          = (const float*)d_in[2];
    const float2* P          = (const float2*)d_in[3];
    float*        out        = (float*)d_out;

    hash_embedding_kernel<<<GRID, TPB>>>(words, hash_table, W, P, out);
}

// round 11
// speedup vs baseline: 1.6345x; 1.6345x over previous
#include <cuda_runtime.h>
#include <cstdint>

// HashEmbedding: B*L=819200 tokens, H=2, E=64, out=[emb(64), pv0, pv1] f32
// d_in: words int32[819200], hash_table int32[1000000,2],
//       W f32[100000,64], P f32[1000000,2]

static constexpr int NTOK  = 16384 * 50;   // 819200
static constexpr int EMBED = 64;
static constexpr int OUTW  = EMBED + 2;    // 66
static constexpr int GRP   = 8;            // tokens per group (R7-proven inner shape)
static constexpr int NGRP  = 4;            // static sequential groups per warp
static constexpr int TPW   = GRP * NGRP;   // 32 tokens per warp
static constexpr int TPB   = 256;

__global__ void __launch_bounds__(TPB)
hash_embedding_kernel(const int*    __restrict__ words,
                      const int2*   __restrict__ hash_table,
                      const float*  __restrict__ W,
                      const float2* __restrict__ P2,
                      float*        __restrict__ out)
{
    const int warp = (blockIdx.x * blockDim.x + threadIdx.x) >> 5;
    const int lane = threadIdx.x & 31;
    const int base = warp * TPW;
    if (base >= NTOK) return;
    const float* Pf = reinterpret_cast<const float*>(P2);

    // ---- Scalar phase, amortized over 32 tokens: lane t owns token base+t.
    // words load is fully coalesced (32 consecutive ints = 128B). One LDG per
    // stage covers all 32 tokens' indices/weights/pvals. ----
    const int    tok = base + lane;
    const int    w   = __ldg(&words[tok]);
    const int2   h   = __ldg(&hash_table[w]);
    const float2 pwv = __ldg(&P2[w]);

    {   // pvals: gather + scattered store, all 32 tokens in 3 instructions
        float2 pv;
        pv.x = __ldg(&Pf[(size_t)h.x * 2 + 0]);
        pv.y = __ldg(&Pf[(size_t)h.y * 2 + 1]);
        *reinterpret_cast<float2*>(out + (size_t)tok * OUTW + EMBED) = pv;
    }

    // ---- 4 sequential R7-style groups: burst 16 W-row gathers (8B/lane,
    // coalesced 256B rows), then consume+store. Registers reused per group;
    // fully static — no loop-carried state, no spills. ----
#pragma unroll
    for (int g = 0; g < NGRP; g++) {
        const int gbase = base + g * GRP;

        float2 a[GRP], b[GRP];
#pragma unroll
        for (int t = 0; t < GRP; t++) {
            const int src = g * GRP + t;                    // owning lane
            const int hx = __shfl_sync(0xffffffffu, h.x, src);
            const int hy = __shfl_sync(0xffffffffu, h.y, src);
            a[t] = __ldg(reinterpret_cast<const float2*>(W + (size_t)hx * EMBED) + lane);
            b[t] = __ldg(reinterpret_cast<const float2*>(W + (size_t)hy * EMBED) + lane);
        }

#pragma unroll
        for (int t = 0; t < GRP; t++) {
            const int src = g * GRP + t;
            const float px = __shfl_sync(0xffffffffu, pwv.x, src);
            const float py = __shfl_sync(0xffffffffu, pwv.y, src);
            float2 e;
            e.x = fmaf(a[t].x, px, b[t].x * py);
            e.y = fmaf(a[t].y, px, b[t].y * py);
            float* o = out + (size_t)(gbase + t) * OUTW;   // 264B stride, 8B aligned
            reinterpret_cast<float2*>(o)[lane] = e;        // cols 0..63
        }
    }
}

extern "C" void kernel_launch(void* const* d_in, const int* in_sizes, int n_in,
                              void* d_out, int out_size)
{
    const int*    words      = (const int*)d_in[0];
    const int2*   hash_table = (const int2*)d_in[1];
    const float*  W          = (const float*)d_in[2];
    const float2* P          = (const float2*)d_in[3];
    float*        out        = (float*)d_out;

    const int tokens_per_block = (TPB / 32) * TPW;                        // 256
    const int blocks = (NTOK + tokens_per_block - 1) / tokens_per_block;  // 3200
    hash_embedding_kernel<<<blocks, TPB>>>(words, hash_table, W, P, out);
}

// round 12
// speedup vs baseline: 1.6921x; 1.0353x over previous
#include <cuda_runtime.h>
#include <cstdint>

// HashEmbedding: B*L=819200 tokens, H=2, E=64, out=[emb(64), pv0, pv1] f32
// d_in: words int32[819200], hash_table int32[1000000,2],
//       W f32[100000,64], P f32[1000000,2]

static constexpr int NTOK  = 16384 * 50;   // 819200
static constexpr int EMBED = 64;
static constexpr int OUTW  = EMBED + 2;    // 66
static constexpr int TPW   = 8;            // tokens per warp
static constexpr int NPAIR = TPW / 2;      // 4 token-pairs, half-warp per token
static constexpr int TPB   = 256;

// 40-reg budget (6 blocks/SM): fits the 8xLDG.128 landing window (32 regs)
// plus scalars without the 32-reg fold that serialized R7/R11's bursts.
__global__ void __launch_bounds__(TPB, 6)
hash_embedding_kernel(const int*    __restrict__ words,
                      const int2*   __restrict__ hash_table,
                      const float*  __restrict__ W,
                      const float2* __restrict__ P2,
                      float*        __restrict__ out)
{
    const int warp = (blockIdx.x * blockDim.x + threadIdx.x) >> 5;
    const int lane = threadIdx.x & 31;
    const int base = warp * TPW;
    if (base >= NTOK) return;
    const float* Pf = reinterpret_cast<const float*>(P2);

    // ---- Distributed scalar phase (R7-proven): lane t (mod 8) owns token
    // base+t; replicated addrs dedup in-warp -> one LDG per stage / 8 tokens. ----
    const int    tok = base + (lane & 7);
    const int    w   = __ldg(&words[tok]);
    const int2   h   = __ldg(&hash_table[w]);
    const float2 pwv = __ldg(&P2[w]);

    if (lane < TPW) {
        float2 pv;
        pv.x = __ldg(&Pf[(size_t)h.x * 2 + 0]);
        pv.y = __ldg(&Pf[(size_t)h.y * 2 + 1]);
        *reinterpret_cast<float2*>(out + (size_t)tok * OUTW + EMBED) = pv;
    }

    // ---- W gathers as LDG.128, half-warp per token: lanes 0-15 -> token 2p,
    // lanes 16-31 -> token 2p+1. 8 instructions keep all 16 rows (4KB) in
    // flight within 32 landing regs — 2x the in-flight bytes of LDG.64. ----
    const int half = lane >> 4;        // 0: even token of pair, 1: odd
    const int col  = lane & 15;        // float4 index within row (16 x 16B = 256B)

    float4 a[NPAIR], b[NPAIR];
#pragma unroll
    for (int p = 0; p < NPAIR; p++) {
        const int src = 2 * p + half;  // owning lane of my token's scalars
        const int hx = __shfl_sync(0xffffffffu, h.x, src);
        const int hy = __shfl_sync(0xffffffffu, h.y, src);
        a[p] = __ldg(reinterpret_cast<const float4*>(W + (size_t)hx * EMBED) + col);
        b[p] = __ldg(reinterpret_cast<const float4*>(W + (size_t)hy * EMBED) + col);
    }

    // ---- Consume in order, store 16B per lane as 2x STG.64 (264B token
    // stride is 8B-aligned; 16B only for even tokens, so no STG.128). ----
#pragma unroll
    for (int p = 0; p < NPAIR; p++) {
        const int src = 2 * p + half;
        const float px = __shfl_sync(0xffffffffu, pwv.x, src);
        const float py = __shfl_sync(0xffffffffu, pwv.y, src);

        float4 e;
        e.x = fmaf(a[p].x, px, b[p].x * py);
        e.y = fmaf(a[p].y, px, b[p].y * py);
        e.z = fmaf(a[p].z, px, b[p].z * py);
        e.w = fmaf(a[p].w, px, b[p].w * py);

        float* o = out + (size_t)(base + 2 * p + half) * OUTW + col * 4;
        reinterpret_cast<float2*>(o)[0] = make_float2(e.x, e.y);
        reinterpret_cast<float2*>(o)[1] = make_float2(e.z, e.w);
    }
}

extern "C" void kernel_launch(void* const* d_in, const int* in_sizes, int n_in,
                              void* d_out, int out_size)
{
    const int*    words      = (const int*)d_in[0];
    const int2*   hash_table = (const int2*)d_in[1];
    const float*  W          = (const float*)d_in[2];
    const float2* P          = (const float2*)d_in[3];
    float*        out        = (float*)d_out;

    const int tokens_per_block = (TPB / 32) * TPW;                        // 64
    const int blocks = (NTOK + tokens_per_block - 1) / tokens_per_block;  // 12800
    hash_embedding_kernel<<<blocks, TPB>>>(words, hash_table, W, P, out);
}

// round 13
// speedup vs baseline: 1.9895x; 1.1758x over previous
#include <cuda_runtime.h>
#include <cstdint>

// HashEmbedding: B*L=819200 tokens, H=2, E=64, out=[emb(64), pv0, pv1] f32
// d_in: words int32[819200], hash_table int32[1000000,2],
//       W f32[100000,64], P f32[1000000,2]

static constexpr int NTOK  = 16384 * 50;   // 819200
static constexpr int EMBED = 64;
static constexpr int OUTW  = EMBED + 2;    // 66
static constexpr int GRP   = 8;            // tokens per inner group (R7 shape)
static constexpr int NGRP  = 2;            // static groups (4 triggered reg-fold; 2 is safe)
static constexpr int TPW   = GRP * NGRP;   // 16 tokens per warp
static constexpr int TPB   = 256;

// 40-reg budget (6 blocks/SM, 75% occ): room for the 8x-LDG.64 landing window
// plus the 2-group scalar state without ptxas's 32-reg fold (R11) or spills.
__global__ void __launch_bounds__(TPB, 6)
hash_embedding_kernel(const int*    __restrict__ words,
                      const int2*   __restrict__ hash_table,
                      const float*  __restrict__ W,
                      const float2* __restrict__ P2,
                      float*        __restrict__ out)
{
    const int warp = (blockIdx.x * blockDim.x + threadIdx.x) >> 5;
    const int lane = threadIdx.x & 31;
    const int base = warp * TPW;
    if (base >= NTOK) return;
    const float* Pf = reinterpret_cast<const float*>(P2);

    // ---- Scalar phase amortized over 16 tokens: lane t (mod 16) owns token
    // base+t. Replicated addrs dedup in-warp: one LDG per stage / 16 tokens. ----
    const int    tok = base + (lane & 15);
    const int    w   = __ldg(&words[tok]);
    const int2   h   = __ldg(&hash_table[w]);
    const float2 pwv = __ldg(&P2[w]);

    if (lane < TPW) {  // pvals: one gather + one scattered store for 16 tokens
        float2 pv;
        pv.x = __ldg(&Pf[(size_t)h.x * 2 + 0]);
        pv.y = __ldg(&Pf[(size_t)h.y * 2 + 1]);
        *reinterpret_cast<float2*>(out + (size_t)tok * OUTW + EMBED) = pv;
    }

    // ---- Two sequential R7 groups: burst 16 LDG.64 W-row gathers (8B/lane,
    // coalesced 256B rows), scalars via SHFL (ALU pipe), consume, store. ----
#pragma unroll
    for (int g = 0; g < NGRP; g++) {
        const int gbase = base + g * GRP;

        float2 a[GRP], b[GRP];
#pragma unroll
        for (int t = 0; t < GRP; t++) {
            const int src = g * GRP + t;   // owning lane (0..15)
            const int hx = __shfl_sync(0xffffffffu, h.x, src);
            const int hy = __shfl_sync(0xffffffffu, h.y, src);
            a[t] = __ldg(reinterpret_cast<const float2*>(W + (size_t)hx * EMBED) + lane);
            b[t] = __ldg(reinterpret_cast<const float2*>(W + (size_t)hy * EMBED) + lane);
        }

#pragma unroll
        for (int t = 0; t < GRP; t++) {
            const int src = g * GRP + t;
            const float px = __shfl_sync(0xffffffffu, pwv.x, src);
            const float py = __shfl_sync(0xffffffffu, pwv.y, src);
            float2 e;
            e.x = fmaf(a[t].x, px, b[t].x * py);
            e.y = fmaf(a[t].y, px, b[t].y * py);
            float* o = out + (size_t)(gbase + t) * OUTW;   // 264B stride, 8B aligned
            reinterpret_cast<float2*>(o)[lane] = e;        // cols 0..63
        }
    }
}

extern "C" void kernel_launch(void* const* d_in, const int* in_sizes, int n_in,
                              void* d_out, int out_size)
{
    const int*    words      = (const int*)d_in[0];
    const int2*   hash_table = (const int2*)d_in[1];
    const float*  W          = (const float*)d_in[2];
    const float2* P          = (const float2*)d_in[3];
    float*        out        = (float*)d_out;

    const int tokens_per_block = (TPB / 32) * TPW;                        // 128
    const int blocks = (NTOK + tokens_per_block - 1) / tokens_per_block;  // 6400
    hash_embedding_kernel<<<blocks, TPB>>>(words, hash_table, W, P, out);
}